// round 14
// baseline (speedup 1.0000x reference)
#include <cuda_runtime.h>
#include <math.h>

#define BATCH 4
#define CHANS 3
#define HDIM 512
#define WDIM 512
#define NPLANES 32
#define MAX_COC 50.0f
#define KMAX 31
#define HALO 15
#define NSYM 16

#define R 8                          // outputs per thread, stacked in y
#define BTX 32
#define BTY 4
#define NTHREADS (BTX*BTY)           // 128
#define OUTROWS (BTY*R)              // 32
#define TILE_H (OUTROWS + 2*HALO)    // 62
#define NROWS (KMAX + R - 1)         // 38
#define NPQ 8

// Four tile copies (float offsets). All pair reads land 8B-aligned:
//  F1[sy*46+i]  = t(gy, bx0+i)      — right pairs, even lanes (idx = tx+2q)
//  F2[sy*46+i]  = t(gy, bx0+1+i)    — right pairs, odd lanes  (idx = tx-1+2q)
//  RV1[sy*46+i] = t(gy, bx0+31-i)   — left pairs, odd lanes   (idx = 31-tx+2q)
//  RV2[sy*48+i] = t(gy, bx0+32-i)   — left pairs, even lanes  (idx = 32-tx+2q)
#define OFF_F1  0
#define OFF_F2  (OFF_F1 + TILE_H*46)          // 2852
#define OFF_RV1 (OFF_F2 + TILE_H*46)          // 5704
#define OFF_RV2 (OFF_RV1 + TILE_H*46)         // 8556
#define OFF_GS  (OFF_RV2 + TILE_H*48)         // 11532
#define SMEM_FLOATS (OFF_GS + NSYM*NPLANES)   // 12044 floats = 48176 B

typedef unsigned long long u64;

__device__ __forceinline__ u64 ffma2(u64 a, u64 b, u64 c) {
    u64 d; asm("fma.rn.f32x2 %0, %1, %2, %3;" : "=l"(d) : "l"(a), "l"(b), "l"(c)); return d;
}
__device__ __forceinline__ u64 fmul2(u64 a, u64 b) {
    u64 d; asm("mul.rn.f32x2 %0, %1, %2;" : "=l"(d) : "l"(a), "l"(b)); return d;
}
__device__ __forceinline__ u64 fadd2(u64 a, u64 b) {
    u64 d; asm("add.rn.f32x2 %0, %1, %2;" : "=l"(d) : "l"(a), "l"(b)); return d;
}
__device__ __forceinline__ u64 pk(float lo, float hi) {
    u64 r; asm("mov.b64 %0, {%1, %2};" : "=l"(r) : "f"(lo), "f"(hi)); return r;
}
__device__ __forceinline__ void upk(float& lo, float& hi, u64 v) {
    asm("mov.b64 {%0, %1}, %2;" : "=f"(lo), "=f"(hi) : "l"(v));
}
// Runtime offset: the q-loop is fully unrolled, so (a + const) folds into the
// LDS immediate field in SASS.
__device__ __forceinline__ u64 lds64(unsigned int a) {
    u64 v; asm("ld.shared.b64 %0, [%1];" : "=l"(v) : "r"(a)); return v;
}

__global__ __launch_bounds__(NTHREADS, 3) void dof_kernel(
    const float* __restrict__ img,
    const float* __restrict__ coc,
    float* __restrict__ out)
{
    __shared__ float smem[SMEM_FLOATS];
    float* gs = smem + OFF_GS;                   // gs[m*32+p]

    const int tx = threadIdx.x, ty = threadIdx.y;
    const int tid = ty * BTX + tx;
    const int bx0 = blockIdx.x * BTX;
    const int by0 = blockIdx.y * OUTROWS;
    const int z   = blockIdx.z;            // z = b*CHANS + ch
    const int b   = z / CHANS;
    const int planeHW = HDIM * WDIM;
    const float step = MAX_COC / (float)(NPLANES - 1);

    // ---- Per-plane symmetric Gaussian half table gs[m][p] ----
    if (tid < NPLANES) {
        const int p = tid;
        float g[KMAX];
        if (p == 0) {
            #pragma unroll
            for (int j = 0; j < KMAX; j++) g[j] = 0.f;
            g[HALO] = 1.f;
        } else {
            const float cocp  = (float)p * step;
            const float sigma = cocp / 2.355f;
            int k = (int)(2.f * cocp + 1.f);
            if ((k & 1) == 0) k++;
            k = min(k, KMAX);
            const int half = k >> 1;
            const float inv2s2 = 1.f / (2.f * sigma * sigma);
            float s = 0.f;
            #pragma unroll
            for (int j = 0; j < KMAX; j++) {
                const int d = j - HALO;
                const int ad = (d < 0) ? -d : d;
                float v = (ad <= half) ? expf(-(float)(d*d) * inv2s2) : 0.f;
                g[j] = v; s += v;
            }
            const float inv = 1.f / s;
            #pragma unroll
            for (int j = 0; j < KMAX; j++) g[j] *= inv;
        }
        #pragma unroll
        for (int m = 0; m < NSYM; m++) gs[m * NPLANES + p] = g[HALO + m];
    }

    // ---- Build the 4 tile copies (zero-pad outside image) ----
    const float* imgP = img + (size_t)z * planeHW;
    // F1 / F2 / RV1 : 62 x 46 each
    for (int idx = tid; idx < TILE_H * 46; idx += NTHREADS) {
        const int sy = idx / 46, i = idx - sy * 46;
        const int gy = by0 - HALO + sy;
        const bool okY = (gy >= 0) & (gy < HDIM);
        const int rowbase = gy * WDIM;
        int gx1 = bx0 + i;                         // F1
        smem[OFF_F1 + sy * 46 + i] =
            (okY & (gx1 < WDIM)) ? imgP[rowbase + gx1] : 0.f;
        int gx2 = bx0 + 1 + i;                     // F2
        smem[OFF_F2 + sy * 46 + i] =
            (okY & (gx2 < WDIM)) ? imgP[rowbase + gx2] : 0.f;
        int gx3 = bx0 + 31 - i;                    // RV1
        smem[OFF_RV1 + sy * 46 + i] =
            (okY & (gx3 >= 0) & (gx3 < WDIM)) ? imgP[rowbase + gx3] : 0.f;
    }
    // RV2 : 62 x 48
    for (int idx = tid; idx < TILE_H * 48; idx += NTHREADS) {
        const int sy = idx / 48, i = idx - sy * 48;
        const int gy = by0 - HALO + sy;
        const bool okY = (gy >= 0) & (gy < HDIM);
        int gx = bx0 + 32 - i;
        smem[OFF_RV2 + sy * 48 + i] =
            (okY & (gx >= 0) & (gx < WDIM)) ? imgP[gy * WDIM + gx] : 0.f;
    }
    __syncthreads();

    const int x   = bx0 + tx;
    const int tyR = ty * R;

    // ---- Per-output plane + packed symmetric horizontal weights ----
    int pj[R];
    u64 hp[R][NPQ];          // 128 registers of weights
    #pragma unroll
    for (int j = 0; j < R; j++) {
        const int y = by0 + tyR + j;
        float c = coc[b * planeHW + y * WDIM + x];
        int p = (int)floorf(c / step + 0.5f);
        p = max(0, min(NPLANES - 1, p));
        pj[j] = p;
        // q=0: s-pair lo holds 2*t[x] -> halve g0
        hp[j][0] = pk(gs[0 * NPLANES + p] * 0.5f, gs[1 * NPLANES + p]);
        #pragma unroll
        for (int q = 1; q < NPQ; q++) {
            hp[j][q] = pk(gs[(2*q) * NPLANES + p],
                          gs[(2*q + 1) * NPLANES + p]);
        }
    }

    // ---- Per-lane aligned pair-read bases (bytes) ----
    const unsigned int smemB = (unsigned int)__cvta_generic_to_shared(smem);
    const bool evenLane = ((tx & 1) == 0);
    const int rBaseF = evenLane ? (OFF_F1 + tx)        : (OFF_F2 + (tx - 1));
    const int lBaseF = evenLane ? (OFF_RV2 + (32 - tx)) : (OFF_RV1 + (31 - tx));
    const int lStr   = evenLane ? 48 : 46;
    unsigned int rA = smemB + (unsigned int)(rBaseF + tyR * 46)  * 4u;
    unsigned int lA = smemB + (unsigned int)(lBaseF + tyR * lStr) * 4u;
    const unsigned int rInc = 46u * 4u;
    const unsigned int lInc = (unsigned int)lStr * 4u;

    float acc[R];
    #pragma unroll
    for (int j = 0; j < R; j++) acc[j] = 0.f;

    // ---- Main gather: full unroll, q-outer / j-inner ----
    #pragma unroll
    for (int rr = 0; rr < NROWS; rr++) {
        u64 rsp[R];
        // q = 0 : fadd2 gives {2*t[x], t[x-1]+t[x+1]} (halved g0 compensates)
        {
            const u64 sp = fadd2(lds64(lA), lds64(rA));
            #pragma unroll
            for (int j = 0; j < R; j++) {
                const int vy = rr - j;
                if (vy >= 0 && vy <= KMAX - 1)
                    rsp[j] = fmul2(hp[j][0], sp);
            }
        }
        #pragma unroll
        for (int q = 1; q < NPQ; q++) {
            const u64 sp = fadd2(lds64(lA + 8u*(unsigned)q),
                                 lds64(rA + 8u*(unsigned)q));
            #pragma unroll
            for (int j = 0; j < R; j++) {
                const int vy = rr - j;
                if (vy >= 0 && vy <= KMAX - 1)
                    rsp[j] = ffma2(hp[j][q], sp, rsp[j]);
            }
        }
        // vertical weight + scalar accumulate
        #pragma unroll
        for (int j = 0; j < R; j++) {
            const int vy = rr - j;                 // compile-time per (rr,j)
            if (vy >= 0 && vy <= KMAX - 1) {
                const int m = (vy >= HALO) ? (vy - HALO) : (HALO - vy);
                const float gv = gs[m * NPLANES + pj[j]];  // conflict-free LDS
                float lo, hi; upk(lo, hi, rsp[j]);
                acc[j] = fmaf(gv, lo + hi, acc[j]);
            }
        }
        rA += rInc; lA += lInc;
    }

    #pragma unroll
    for (int j = 0; j < R; j++) {
        const int y = by0 + tyR + j;
        out[(size_t)z * planeHW + y * WDIM + x] = acc[j];
    }
}

extern "C" void kernel_launch(void* const* d_in, const int* in_sizes, int n_in,
                              void* d_out, int out_size)
{
    const float* img = (const float*)d_in[0];   // [4,3,512,512]
    const float* coc = (const float*)d_in[1];   // [4,1,512,512]
    float* out = (float*)d_out;                 // [4,3,512,512]

    dim3 block(BTX, BTY);
    dim3 grid(WDIM / BTX, HDIM / OUTROWS, BATCH * CHANS);
    dof_kernel<<<grid, block>>>(img, coc, out);
}

// round 15
// speedup vs baseline: 1.1995x; 1.1995x over previous
#include <cuda_runtime.h>
#include <math.h>
#include <string.h>

#define BATCH 4
#define CHANS 3
#define HDIM 512
#define WDIM 512
#define NPLANES 32
#define MAX_COC 50.0f
#define KMAX 31
#define HALO 15
#define NSYM 16

#define R 8                          // outputs per thread, stacked in y
#define BTX 32
#define BTY 4
#define NTHREADS (BTX*BTY)           // 128
#define OUTROWS (BTY*R)              // 32
#define TILE_W (BTX + 2*HALO)        // 62
#define TILE_H (OUTROWS + 2*HALO)    // 62
#define NROWS (KMAX + R - 1)         // 38
#define NPQ 8

typedef unsigned long long u64;

__device__ __forceinline__ u64 pk(float lo, float hi) {
    u64 r; asm("mov.b64 %0, {%1, %2};" : "=l"(r) : "f"(lo), "f"(hi)); return r;
}
__device__ __forceinline__ void upk(float& lo, float& hi, u64 v) {
    asm("mov.b64 {%0, %1}, %2;" : "=f"(lo), "=f"(hi) : "l"(v));
}
__device__ __forceinline__ u64 ffma2(u64 a, u64 b, u64 c) {
    u64 d; asm("fma.rn.f32x2 %0, %1, %2, %3;" : "=l"(d) : "l"(a), "l"(b), "l"(c)); return d;
}
__device__ __forceinline__ u64 fmul2(u64 a, u64 b) {
    u64 d; asm("mul.rn.f32x2 %0, %1, %2;" : "=l"(d) : "l"(a), "l"(b)); return d;
}
// Bitcast float2 -> u64 (same aligned register pair; no SASS instruction)
__device__ __forceinline__ u64 as_u64(const float2& v) {
    u64 r; memcpy(&r, &v, 8); return r;
}

__global__ __launch_bounds__(NTHREADS, 3) void dof_kernel(
    const float* __restrict__ img,
    const float* __restrict__ coc,
    float* __restrict__ out)
{
    __shared__ float tile[TILE_H * TILE_W];              // 15376 B
    __shared__ float gs[NSYM * NPLANES];                 // gs[m*32+p]: 2048 B

    const int tx = threadIdx.x, ty = threadIdx.y;
    const int tid = ty * BTX + tx;
    const int bx0 = blockIdx.x * BTX;
    const int by0 = blockIdx.y * OUTROWS;
    const int z   = blockIdx.z;            // z = b*CHANS + ch
    const int b   = z / CHANS;
    const int planeHW = HDIM * WDIM;
    const float step = MAX_COC / (float)(NPLANES - 1);

    // ---- Per-plane symmetric Gaussian half table gs[m][p] ----
    if (tid < NPLANES) {
        const int p = tid;
        float g[KMAX];
        if (p == 0) {
            #pragma unroll
            for (int j = 0; j < KMAX; j++) g[j] = 0.f;
            g[HALO] = 1.f;
        } else {
            const float cocp  = (float)p * step;
            const float sigma = cocp / 2.355f;
            int k = (int)(2.f * cocp + 1.f);
            if ((k & 1) == 0) k++;
            k = min(k, KMAX);
            const int half = k >> 1;
            const float inv2s2 = 1.f / (2.f * sigma * sigma);
            float s = 0.f;
            #pragma unroll
            for (int j = 0; j < KMAX; j++) {
                const int d = j - HALO;
                const int ad = (d < 0) ? -d : d;
                float v = (ad <= half) ? expf(-(float)(d*d) * inv2s2) : 0.f;
                g[j] = v; s += v;
            }
            const float inv = 1.f / s;
            #pragma unroll
            for (int j = 0; j < KMAX; j++) g[j] *= inv;
        }
        #pragma unroll
        for (int m = 0; m < NSYM; m++) gs[m * NPLANES + p] = g[HALO + m];
    }

    // ---- Cooperative tile load (this block's channel, zero-pad) ----
    const float* imgP = img + (size_t)z * planeHW;
    for (int idx = tid; idx < TILE_H * TILE_W; idx += NTHREADS) {
        const int sy = idx / TILE_W;
        const int sx = idx - sy * TILE_W;
        const int gy = by0 - HALO + sy;
        const int gx = bx0 - HALO + sx;
        const bool inb = (gy >= 0) & (gy < HDIM) & (gx >= 0) & (gx < WDIM);
        tile[idx] = inb ? imgP[gy * WDIM + gx] : 0.f;
    }
    __syncthreads();

    const int x   = bx0 + tx;
    const int tyR = ty * R;

    // ---- Per-output plane + packed symmetric weights (ALL g values live here;
    //      vertical weight gv is a compile-time register half of hp) ----
    float2 hp[R][NPQ];          // 128 registers of weights
    #pragma unroll
    for (int j = 0; j < R; j++) {
        const int y = by0 + tyR + j;
        float c = coc[b * planeHW + y * WDIM + x];
        int p = (int)floorf(c / step + 0.5f);
        p = max(0, min(NPLANES - 1, p));
        #pragma unroll
        for (int q = 0; q < NPQ; q++) {
            hp[j][q] = make_float2(gs[(2*q) * NPLANES + p],
                                   gs[(2*q + 1) * NPLANES + p]);
        }
    }

    u64 acc[R];
    #pragma unroll
    for (int j = 0; j < R; j++) acc[j] = pk(0.f, 0.f);

    // ---- Main gather: full unroll, q-outer / j-inner ----
    #pragma unroll
    for (int rr = 0; rr < NROWS; rr++) {
        const float* rowp = tile + (tyR + rr) * TILE_W + tx;
        u64 rsp[R];
        // q = 0 : sp0 = {t[c], t[c-1]+t[c+1]}
        {
            const u64 sp0 = pk(rowp[HALO], rowp[HALO-1] + rowp[HALO+1]);
            #pragma unroll
            for (int j = 0; j < R; j++) {
                const int vy = rr - j;
                if (vy >= 0 && vy <= KMAX - 1)
                    rsp[j] = fmul2(as_u64(hp[j][0]), sp0);
            }
        }
        // q = 1..7 : sp = {t[c-2q]+t[c+2q], t[c-2q-1]+t[c+2q+1]}
        #pragma unroll
        for (int q = 1; q < NPQ; q++) {
            const int m0 = 2*q, m1 = 2*q + 1;
            const u64 sp = pk(rowp[HALO-m0] + rowp[HALO+m0],
                              rowp[HALO-m1] + rowp[HALO+m1]);
            #pragma unroll
            for (int j = 0; j < R; j++) {
                const int vy = rr - j;
                if (vy >= 0 && vy <= KMAX - 1)
                    rsp[j] = ffma2(as_u64(hp[j][q]), sp, rsp[j]);
            }
        }
        // vertical weight from hp register halves + accumulate
        #pragma unroll
        for (int j = 0; j < R; j++) {
            const int vy = rr - j;                 // compile-time per (rr,j)
            if (vy >= 0 && vy <= KMAX - 1) {
                const int m = (vy >= HALO) ? (vy - HALO) : (HALO - vy);
                const float gv = (m & 1) ? hp[j][m >> 1].y : hp[j][m >> 1].x;
                acc[j] = ffma2(pk(gv, gv), rsp[j], acc[j]);
            }
        }
    }

    #pragma unroll
    for (int j = 0; j < R; j++) {
        float lo, hi; upk(lo, hi, acc[j]);
        const int y = by0 + tyR + j;
        out[(size_t)z * planeHW + y * WDIM + x] = lo + hi;
    }
}

extern "C" void kernel_launch(void* const* d_in, const int* in_sizes, int n_in,
                              void* d_out, int out_size)
{
    const float* img = (const float*)d_in[0];   // [4,3,512,512]
    const float* coc = (const float*)d_in[1];   // [4,1,512,512]
    float* out = (float*)d_out;                 // [4,3,512,512]

    dim3 block(BTX, BTY);
    dim3 grid(WDIM / BTX, HDIM / OUTROWS, BATCH * CHANS);
    dof_kernel<<<grid, block>>>(img, coc, out);
}